// round 6
// baseline (speedup 1.0000x reference)
#include <cuda_runtime.h>
#include <cuda_bf16.h>
#include <cstdint>

// ---------------------------------------------------------------------------
// SwinBasicBlock: out = 2 * (window_attention(LN(x)) + x), BCHW.
// MLP branch is dead code in the reference -> skipped.
// B=8, C=256, H=W=128, WS=8, NH=8, hd=32, SHIFT=4, M = 131072 rows.
// ---------------------------------------------------------------------------

#define Cdim 256
#define Hdim 128
#define Wdim 128
#define MROWS 131072
#define NWIN 2048
#define NSM 148

// Scratch (device globals; allocation APIs forbidden)
__device__ __nv_bfloat16 g_Y[MROWS * Cdim];       // LN output, bf16
__device__ __nv_bfloat16 g_QKV[MROWS * 3 * Cdim]; // qkv, bf16
__device__ __nv_bfloat16 g_O[MROWS * Cdim];       // attn out, bf16
__device__ __nv_bfloat16 g_WTq[768 * 256];        // w_qkv^T  [n][k]
__device__ __nv_bfloat16 g_WTp[256 * 256];        // w_proj^T [n][k]

// ------------------------------ PTX helpers --------------------------------
__device__ __forceinline__ void cp16(uint32_t dst, const void* src) {
    asm volatile("cp.async.cg.shared.global [%0], [%1], 16;\n"
                 :: "r"(dst), "l"(src));
}
__device__ __forceinline__ void cp_commit() {
    asm volatile("cp.async.commit_group;\n");
}
template <int N> __device__ __forceinline__ void cp_wait() {
    asm volatile("cp.async.wait_group %0;\n" :: "n"(N));
}
__device__ __forceinline__ void ldsm_x4(uint32_t r[4], uint32_t addr) {
    asm volatile("ldmatrix.sync.aligned.m8n8.x4.shared.b16 {%0,%1,%2,%3}, [%4];\n"
                 : "=r"(r[0]), "=r"(r[1]), "=r"(r[2]), "=r"(r[3]) : "r"(addr));
}
__device__ __forceinline__ void ldsm_x4_t(uint32_t r[4], uint32_t addr) {
    asm volatile("ldmatrix.sync.aligned.m8n8.x4.trans.shared.b16 {%0,%1,%2,%3}, [%4];\n"
                 : "=r"(r[0]), "=r"(r[1]), "=r"(r[2]), "=r"(r[3]) : "r"(addr));
}
__device__ __forceinline__ void mma_bf16(float c[4], const uint32_t a[4],
                                         uint32_t b0, uint32_t b1) {
    asm volatile(
        "mma.sync.aligned.m16n8k16.row.col.f32.bf16.bf16.f32 "
        "{%0,%1,%2,%3},{%4,%5,%6,%7},{%8,%9},{%0,%1,%2,%3};\n"
        : "+f"(c[0]), "+f"(c[1]), "+f"(c[2]), "+f"(c[3])
        : "r"(a[0]), "r"(a[1]), "r"(a[2]), "r"(a[3]), "r"(b0), "r"(b1));
}
__device__ __forceinline__ uint32_t packbf(float lo, float hi) {
    uint32_t r;
    asm("cvt.rn.bf16x2.f32 %0, %1, %2;\n" : "=r"(r) : "f"(hi), "f"(lo));
    return r;
}
__device__ __forceinline__ uint32_t s2u(const void* p) {
    return (uint32_t)__cvta_generic_to_shared(p);
}

// ---------------------------------------------------------------------------
// W0: transpose weights to [N][K] bf16.
// ---------------------------------------------------------------------------
__global__ void wconv(const float* __restrict__ wq, const float* __restrict__ wp) {
    const int idx = blockIdx.x * 256 + threadIdx.x;   // 768*256 threads
    const int n = idx >> 8, k = idx & 255;
    g_WTq[idx] = __float2bfloat16(wq[k * 768 + n]);
    if (n < 256) g_WTp[idx] = __float2bfloat16(wp[k * 256 + n]);
}

// ---------------------------------------------------------------------------
// K1: LayerNorm over C + cyclic shift (-4,-4) + window partition -> bf16 Y.
// ---------------------------------------------------------------------------
__global__ void k1_ln_roll_part(const float* __restrict__ x,
                                const float* __restrict__ gamma,
                                const float* __restrict__ beta,
                                __nv_bfloat16* __restrict__ Y) {
    __shared__ float tile[32][257];
    const int b  = blockIdx.z;
    const int h  = blockIdx.y;
    const int w0 = blockIdx.x * 32;
    const int t  = threadIdx.x;
    const int wl = t & 31;
    const int co = t >> 5;

    const float* xb = x + (long)b * Cdim * Hdim * Wdim;
    #pragma unroll
    for (int cb = 0; cb < Cdim; cb += 8) {
        const int c = cb + co;
        tile[wl][c] = __ldcs(&xb[((long)c * Hdim + h) * Wdim + w0 + wl]);
    }
    __syncthreads();

    const int p = t >> 3, sub = t & 7;
    float s = 0.f, ss = 0.f;
    #pragma unroll
    for (int c = sub; c < Cdim; c += 8) {
        const float v = tile[p][c];
        s += v; ss += v * v;
    }
    #pragma unroll
    for (int off = 4; off > 0; off >>= 1) {
        s  += __shfl_xor_sync(0xffffffffu, s,  off);
        ss += __shfl_xor_sync(0xffffffffu, ss, off);
    }
    const float mean = s * (1.f / Cdim);
    const float var  = ss * (1.f / Cdim) - mean * mean;
    const float inv  = rsqrtf(var + 1e-5f);
    #pragma unroll
    for (int c = sub; c < Cdim; c += 8)
        tile[p][c] = (tile[p][c] - mean) * inv * gamma[c] + beta[c];
    __syncthreads();

    const int h2 = (h - 4) & 127;
    #pragma unroll 4
    for (int p2 = 0; p2 < 32; p2++) {
        const int w2 = (w0 + p2 - 4) & 127;
        const long row = (((long)b * 16 + (h2 >> 3)) * 16 + (w2 >> 3)) * 64
                         + (h2 & 7) * 8 + (w2 & 7);
        Y[row * Cdim + t] = __float2bfloat16(tile[p2][t]);
    }
}

// ---------------------------------------------------------------------------
// K2: bf16 tensor-core GEMM: C[M,N] = A[M,256] @ WT[N][256]^T + bias -> bf16.
// Block 128x128, BK=32, 8 warps, warp tile 64x32, cp.async double buffer.
// ---------------------------------------------------------------------------
#define GP 40   // smem row pitch in halves (80 B: 16B-aligned, conflict-free)

__global__ __launch_bounds__(256)
void bf16_gemm_qkv(const __nv_bfloat16* __restrict__ A,
                   const __nv_bfloat16* __restrict__ WT,
                   const float* __restrict__ bias,
                   __nv_bfloat16* __restrict__ Cb, int N) {
    __shared__ __nv_bfloat16 As[2][128 * GP];
    __shared__ __nv_bfloat16 Bs[2][128 * GP];
    const int K = 256;

    const int t    = threadIdx.x;
    const int warp = t >> 5;
    const int lane = t & 31;
    const int gid  = lane >> 2;
    const int tig  = lane & 3;
    const int wm   = (warp >> 2) * 64;
    const int wn   = (warp & 3) * 32;
    const int bm   = blockIdx.y * 128;
    const int bn   = blockIdx.x * 128;

    const uint32_t asb = s2u(&As[0][0]);
    const uint32_t bsb = s2u(&Bs[0][0]);

    auto loadStage = [&](int st, int k0) {
        #pragma unroll
        for (int i = 0; i < 2; i++) {
            const int ci  = t + i * 256;
            const int row = ci >> 2;
            const int kc  = (ci & 3) * 8;
            cp16(asb + (st * 128 * GP + row * GP + kc) * 2,
                 A + (long)(bm + row) * K + k0 + kc);
            cp16(bsb + (st * 128 * GP + row * GP + kc) * 2,
                 WT + (long)(bn + row) * K + k0 + kc);
        }
        cp_commit();
    };

    float acc[4][4][4];
    #pragma unroll
    for (int i = 0; i < 4; i++)
        #pragma unroll
        for (int j = 0; j < 4; j++)
            #pragma unroll
            for (int r = 0; r < 4; r++) acc[i][j][r] = 0.f;

    loadStage(0, 0);

    const int r16  = lane & 15;
    const int hsel = (lane >> 4) << 3;
    const int sel  = lane >> 3, l8 = lane & 7;

    #pragma unroll 1
    for (int kt = 0; kt < 8; kt++) {
        cp_wait<0>();
        __syncthreads();
        if (kt + 1 < 8) loadStage((kt + 1) & 1, (kt + 1) * 32);

        const int st = kt & 1;
        #pragma unroll
        for (int ks = 0; ks < 2; ks++) {
            uint32_t af[4][4];
            #pragma unroll
            for (int mt = 0; mt < 4; mt++)
                ldsm_x4(af[mt], asb + (st * 128 * GP
                        + (wm + mt * 16 + r16) * GP + ks * 16 + hsel) * 2);
            #pragma unroll
            for (int np = 0; np < 2; np++) {
                const int brow = wn + np * 16 + ((sel & 2) ? 8 : 0) + l8;
                const int bcol = ks * 16 + ((sel & 1) ? 8 : 0);
                uint32_t bf[4];
                ldsm_x4(bf, bsb + (st * 128 * GP + brow * GP + bcol) * 2);
                #pragma unroll
                for (int mt = 0; mt < 4; mt++) {
                    mma_bf16(acc[mt][np * 2],     af[mt], bf[0], bf[1]);
                    mma_bf16(acc[mt][np * 2 + 1], af[mt], bf[2], bf[3]);
                }
            }
        }
        __syncthreads();
    }

    #pragma unroll
    for (int nt = 0; nt < 4; nt++) {
        const int col = bn + wn + nt * 8 + 2 * tig;
        const float b0 = bias[col], b1 = bias[col + 1];
        #pragma unroll
        for (int mt = 0; mt < 4; mt++) {
            const long row = bm + wm + mt * 16 + gid;
            *(uint32_t*)&Cb[row * N + col] =
                packbf(acc[mt][nt][0] + b0, acc[mt][nt][1] + b1);
            *(uint32_t*)&Cb[(row + 8) * N + col] =
                packbf(acc[mt][nt][2] + b0, acc[mt][nt][3] + b1);
        }
    }
}

// ---------------------------------------------------------------------------
// K4E: proj GEMM fused with epilogue: out[b,c,h,w] = 2*(P + x) directly in
// BCHW with window-reverse + roll(+4,+4). P = O @ w_proj^T + bias.
// ---------------------------------------------------------------------------
__global__ __launch_bounds__(256)
void bf16_gemm_proj_epi(const __nv_bfloat16* __restrict__ A,
                        const __nv_bfloat16* __restrict__ WT,
                        const float* __restrict__ bias,
                        const float* __restrict__ x,
                        float* __restrict__ out) {
    __shared__ __nv_bfloat16 As[2][128 * GP];
    __shared__ __nv_bfloat16 Bs[2][128 * GP];
    const int K = 256;

    const int t    = threadIdx.x;
    const int warp = t >> 5;
    const int lane = t & 31;
    const int gid  = lane >> 2;
    const int tig  = lane & 3;
    const int wm   = (warp >> 2) * 64;
    const int wn   = (warp & 3) * 32;
    const int bm   = blockIdx.y * 128;
    const int bn   = blockIdx.x * 128;

    const uint32_t asb = s2u(&As[0][0]);
    const uint32_t bsb = s2u(&Bs[0][0]);

    auto loadStage = [&](int st, int k0) {
        #pragma unroll
        for (int i = 0; i < 2; i++) {
            const int ci  = t + i * 256;
            const int row = ci >> 2;
            const int kc  = (ci & 3) * 8;
            cp16(asb + (st * 128 * GP + row * GP + kc) * 2,
                 A + (long)(bm + row) * K + k0 + kc);
            cp16(bsb + (st * 128 * GP + row * GP + kc) * 2,
                 WT + (long)(bn + row) * K + k0 + kc);
        }
        cp_commit();
    };

    float acc[4][4][4];
    #pragma unroll
    for (int i = 0; i < 4; i++)
        #pragma unroll
        for (int j = 0; j < 4; j++)
            #pragma unroll
            for (int r = 0; r < 4; r++) acc[i][j][r] = 0.f;

    loadStage(0, 0);

    const int r16  = lane & 15;
    const int hsel = (lane >> 4) << 3;
    const int sel  = lane >> 3, l8 = lane & 7;

    #pragma unroll 1
    for (int kt = 0; kt < 8; kt++) {
        cp_wait<0>();
        __syncthreads();
        if (kt + 1 < 8) loadStage((kt + 1) & 1, (kt + 1) * 32);

        const int st = kt & 1;
        #pragma unroll
        for (int ks = 0; ks < 2; ks++) {
            uint32_t af[4][4];
            #pragma unroll
            for (int mt = 0; mt < 4; mt++)
                ldsm_x4(af[mt], asb + (st * 128 * GP
                        + (wm + mt * 16 + r16) * GP + ks * 16 + hsel) * 2);
            #pragma unroll
            for (int np = 0; np < 2; np++) {
                const int brow = wn + np * 16 + ((sel & 2) ? 8 : 0) + l8;
                const int bcol = ks * 16 + ((sel & 1) ? 8 : 0);
                uint32_t bf[4];
                ldsm_x4(bf, bsb + (st * 128 * GP + brow * GP + bcol) * 2);
                #pragma unroll
                for (int mt = 0; mt < 4; mt++) {
                    mma_bf16(acc[mt][np * 2],     af[mt], bf[0], bf[1]);
                    mma_bf16(acc[mt][np * 2 + 1], af[mt], bf[2], bf[3]);
                }
            }
        }
        __syncthreads();
    }

    // fused epilogue: window-reverse + roll + residual, scattered to BCHW
    #pragma unroll
    for (int mt = 0; mt < 4; mt++) {
        #pragma unroll
        for (int rh = 0; rh < 2; rh++) {
            const int row = bm + wm + mt * 16 + gid + rh * 8;
            const int win = row >> 6;
            const int n   = row & 63;
            const int b   = win >> 8;
            const int wh  = (win >> 4) & 15;
            const int ww  = win & 15;
            const int h   = (wh * 8 + (n >> 3) + 4) & 127;
            const int w   = (ww * 8 + (n & 7) + 4) & 127;
            const long pbase = ((long)b * Cdim) * (Hdim * Wdim) + h * Wdim + w;
            #pragma unroll
            for (int nt = 0; nt < 4; nt++) {
                const int c0 = bn + wn + nt * 8 + 2 * tig;
                const long i0 = pbase + (long)c0 * (Hdim * Wdim);
                const long i1 = i0 + (Hdim * Wdim);
                __stcs(&out[i0], 2.f * (acc[mt][nt][rh * 2]     + bias[c0]     + __ldcs(&x[i0])));
                __stcs(&out[i1], 2.f * (acc[mt][nt][rh * 2 + 1] + bias[c0 + 1] + __ldcs(&x[i1])));
            }
        }
    }
}

// ---------------------------------------------------------------------------
// K3: persistent tensor-core windowed attention.
// grid = 148 CTAs x 512 threads; each CTA processes windows cta, cta+148, ...
// Double-buffered swizzled smem (2 x 96 KB): prefetch window i+1 via cp.async
// while computing window i -> DRAM stays busy.
// Layout: per (qkv,head) tile = 64 rows x 64 B; 16B chunk c at row r lives at
// r*64 + ((c ^ ((r>>1)&3))<<4)  -> all 8 LDSM rows hit distinct 16B groups.
// ---------------------------------------------------------------------------
#define WTILE_B 4096            // bytes per (qkv, head) tile
#define BUF_B   (24 * WTILE_B)  // 98304 bytes per window buffer

__device__ __forceinline__ uint32_t swz(int row, int chunk) {
    return (uint32_t)(row * 64 + ((chunk ^ ((row >> 1) & 3)) << 4));
}

__global__ __launch_bounds__(512, 1)
void k3_attention(const __nv_bfloat16* __restrict__ QKV,
                  __nv_bfloat16* __restrict__ O) {
    extern __shared__ __nv_bfloat16 smem[];
    const int t     = threadIdx.x;
    const int wid   = t >> 5;
    const int head  = wid >> 1;
    const int mhalf = wid & 1;      // rows [mhalf*32, mhalf*32+32)
    const int lane  = t & 31;
    const int gid   = lane >> 2;
    const int tig   = lane & 3;

    const uint32_t sb = s2u(smem);

    const int r16  = lane & 15;
    const int hs2  = lane >> 4;        // 0/1: k-half chunk select
    const int sel  = lane >> 3, l8 = lane & 7;
    const int mb   = mhalf * 32;
    const float scale = 0.17677669529663689f;

    auto loadWin = [&](int win, int buf) {
        const __nv_bfloat16* src = QKV + (long)win * (64 * 768);
        const uint32_t db = sb + buf * BUF_B;
        #pragma unroll
        for (int i = 0; i < 12; i++) {
            const int ci    = i * 512 + t;      // 0..6143 16B chunks
            const int token = ci / 96;
            const int c2    = ci % 96;
            const int qkv   = c2 >> 5;
            const int rest  = c2 & 31;
            const int hh    = rest >> 2;
            const int ch    = rest & 3;
            cp16(db + (qkv * 8 + hh) * WTILE_B + swz(token, ch),
                 src + (long)token * 768 + qkv * 256 + hh * 32 + ch * 8);
        }
    };

    const int w0 = blockIdx.x;
    if (w0 < NWIN) loadWin(w0, 0);
    cp_commit();

    int i = 0;
    for (int win = w0; win < NWIN; win += NSM, i++) {
        const int wnext = win + NSM;
        if (wnext < NWIN) loadWin(wnext, (i + 1) & 1);
        cp_commit();
        cp_wait<1>();
        __syncthreads();

        const int buf = i & 1;
        const uint32_t qb = sb + buf * BUF_B + head * WTILE_B;
        const uint32_t kb = sb + buf * BUF_B + (8 + head) * WTILE_B;
        const uint32_t vb = sb + buf * BUF_B + (16 + head) * WTILE_B;

        // ---- S = Q K^T (32x64 rows for this warp), fp32 accum
        float sc[2][8][4];
        #pragma unroll
        for (int mt = 0; mt < 2; mt++)
            #pragma unroll
            for (int nt = 0; nt < 8; nt++)
                #pragma unroll
                for (int r = 0; r < 4; r++) sc[mt][nt][r] = 0.f;

        #pragma unroll
        for (int ks = 0; ks < 2; ks++) {
            uint32_t af[2][4];
            #pragma unroll
            for (int mt = 0; mt < 2; mt++)
                ldsm_x4(af[mt], qb + swz(mb + mt * 16 + r16, ks * 2 + hs2));
            #pragma unroll
            for (int np = 0; np < 4; np++) {
                const int brow = np * 16 + ((sel & 2) ? 8 : 0) + l8;
                uint32_t bf[4];
                ldsm_x4(bf, kb + swz(brow, ks * 2 + (sel & 1)));
                #pragma unroll
                for (int mt = 0; mt < 2; mt++) {
                    mma_bf16(sc[mt][np * 2],     af[mt], bf[0], bf[1]);
                    mma_bf16(sc[mt][np * 2 + 1], af[mt], bf[2], bf[3]);
                }
            }
        }

        // ---- softmax over rows (quad shuffles)
        float ilo[2], ihi[2];
        #pragma unroll
        for (int mt = 0; mt < 2; mt++) {
            float mlo = -1e30f, mhi = -1e30f;
            #pragma unroll
            for (int nt = 0; nt < 8; nt++) {
                mlo = fmaxf(mlo, fmaxf(sc[mt][nt][0], sc[mt][nt][1]));
                mhi = fmaxf(mhi, fmaxf(sc[mt][nt][2], sc[mt][nt][3]));
            }
            mlo = fmaxf(mlo, __shfl_xor_sync(0xffffffffu, mlo, 1));
            mlo = fmaxf(mlo, __shfl_xor_sync(0xffffffffu, mlo, 2));
            mhi = fmaxf(mhi, __shfl_xor_sync(0xffffffffu, mhi, 1));
            mhi = fmaxf(mhi, __shfl_xor_sync(0xffffffffu, mhi, 2));
            float slo = 0.f, shi = 0.f;
            #pragma unroll
            for (int nt = 0; nt < 8; nt++) {
                sc[mt][nt][0] = __expf(scale * (sc[mt][nt][0] - mlo));
                sc[mt][nt][1] = __expf(scale * (sc[mt][nt][1] - mlo));
                sc[mt][nt][2] = __expf(scale * (sc[mt][nt][2] - mhi));
                sc[mt][nt][3] = __expf(scale * (sc[mt][nt][3] - mhi));
                slo += sc[mt][nt][0] + sc[mt][nt][1];
                shi += sc[mt][nt][2] + sc[mt][nt][3];
            }
            slo += __shfl_xor_sync(0xffffffffu, slo, 1);
            slo += __shfl_xor_sync(0xffffffffu, slo, 2);
            shi += __shfl_xor_sync(0xffffffffu, shi, 1);
            shi += __shfl_xor_sync(0xffffffffu, shi, 2);
            ilo[mt] = 1.f / slo;
            ihi[mt] = 1.f / shi;
        }

        // ---- O = P V (32x32 for this warp)
        float oc[2][4][4];
        #pragma unroll
        for (int mt = 0; mt < 2; mt++)
            #pragma unroll
            for (int nt = 0; nt < 4; nt++)
                #pragma unroll
                for (int r = 0; r < 4; r++) oc[mt][nt][r] = 0.f;

        #pragma unroll
        for (int ks = 0; ks < 4; ks++) {   // token chunks of 16
            uint32_t pa[2][4];
            #pragma unroll
            for (int mt = 0; mt < 2; mt++) {
                pa[mt][0] = packbf(sc[mt][2 * ks][0] * ilo[mt], sc[mt][2 * ks][1] * ilo[mt]);
                pa[mt][1] = packbf(sc[mt][2 * ks][2] * ihi[mt], sc[mt][2 * ks][3] * ihi[mt]);
                pa[mt][2] = packbf(sc[mt][2 * ks + 1][0] * ilo[mt], sc[mt][2 * ks + 1][1] * ilo[mt]);
                pa[mt][3] = packbf(sc[mt][2 * ks + 1][2] * ihi[mt], sc[mt][2 * ks + 1][3] * ihi[mt]);
            }
            #pragma unroll
            for (int dp = 0; dp < 2; dp++) {  // dim chunks of 16
                const int vrow = ks * 16 + ((sel & 1) ? 8 : 0) + l8;
                uint32_t vf[4];
                ldsm_x4_t(vf, vb + swz(vrow, dp * 2 + ((sel & 2) >> 1)));
                #pragma unroll
                for (int mt = 0; mt < 2; mt++) {
                    mma_bf16(oc[mt][dp * 2],     pa[mt], vf[0], vf[1]);
                    mma_bf16(oc[mt][dp * 2 + 1], pa[mt], vf[2], vf[3]);
                }
            }
        }

        // ---- store O bf16 [row][256]
        #pragma unroll
        for (int mt = 0; mt < 2; mt++) {
            const long row = (long)win * 64 + mb + mt * 16 + gid;
            #pragma unroll
            for (int nt = 0; nt < 4; nt++) {
                const int col = head * 32 + nt * 8 + 2 * tig;
                *(uint32_t*)&O[row * 256 + col] =
                    packbf(oc[mt][nt][0], oc[mt][nt][1]);
                *(uint32_t*)&O[(row + 8) * 256 + col] =
                    packbf(oc[mt][nt][2], oc[mt][nt][3]);
            }
        }
        __syncthreads();   // all warps done with buf before it is reloaded
    }
}

// ---------------------------------------------------------------------------
extern "C" void kernel_launch(void* const* d_in, const int* in_sizes, int n_in,
                              void* d_out, int out_size) {
    const float* x      = (const float*)d_in[0];
    const float* n1g    = (const float*)d_in[1];
    const float* n1b    = (const float*)d_in[2];
    const float* w_qkv  = (const float*)d_in[3];
    const float* b_qkv  = (const float*)d_in[4];
    const float* w_proj = (const float*)d_in[5];
    const float* b_proj = (const float*)d_in[6];
    float* out = (float*)d_out;

    __nv_bfloat16 *Y, *QKV, *Obuf, *WTq, *WTp;
    cudaGetSymbolAddress((void**)&Y,    g_Y);
    cudaGetSymbolAddress((void**)&QKV,  g_QKV);
    cudaGetSymbolAddress((void**)&Obuf, g_O);
    cudaGetSymbolAddress((void**)&WTq,  g_WTq);
    cudaGetSymbolAddress((void**)&WTp,  g_WTp);

    const int att_smem = 2 * BUF_B;  // 196608 B
    cudaFuncSetAttribute(k3_attention,
                         cudaFuncAttributeMaxDynamicSharedMemorySize, att_smem);

    // W0: weight transpose+convert
    wconv<<<768, 256>>>(w_qkv, w_proj);

    // K1: LN + shift + window partition -> bf16
    k1_ln_roll_part<<<dim3(4, 128, 8), 256>>>(x, n1g, n1b, Y);

    // K2: QKV GEMM (bf16 tensor cores)
    bf16_gemm_qkv<<<dim3(6, 1024), 256>>>(Y, WTq, b_qkv, QKV, 768);

    // K3: persistent double-buffered windowed attention
    k3_attention<<<NSM, 512, att_smem>>>(QKV, Obuf);

    // K4E: proj GEMM + fused reverse/roll/residual epilogue -> BCHW out
    bf16_gemm_proj_epi<<<dim3(2, 1024), 256>>>(Obuf, WTp, b_proj, x, out);
}

// round 7
// speedup vs baseline: 1.3604x; 1.3604x over previous
#include <cuda_runtime.h>
#include <cuda_bf16.h>
#include <cstdint>

// ---------------------------------------------------------------------------
// SwinBasicBlock: out = 2 * (window_attention(LN(x)) + x), BCHW.
// MLP branch is dead code in the reference -> skipped.
// B=8, C=256, H=W=128, WS=8, NH=8, hd=32, SHIFT=4, M = 131072 rows.
// ---------------------------------------------------------------------------

#define Cdim 256
#define Hdim 128
#define Wdim 128
#define MROWS 131072
#define NWIN 2048
#define NSM 148

// Scratch (device globals; allocation APIs forbidden)
__device__ __nv_bfloat16 g_Y[MROWS * Cdim];       // LN output, bf16
__device__ __nv_bfloat16 g_QKV[MROWS * 3 * Cdim]; // qkv, bf16
__device__ __nv_bfloat16 g_O[MROWS * Cdim];       // attn out, bf16
__device__ __nv_bfloat16 g_WTq[768 * 256];        // w_qkv^T  [n][k]
__device__ __nv_bfloat16 g_WTp[256 * 256];        // w_proj^T [n][k]

// ------------------------------ PTX helpers --------------------------------
__device__ __forceinline__ void cp16(uint32_t dst, const void* src) {
    asm volatile("cp.async.cg.shared.global [%0], [%1], 16;\n"
                 :: "r"(dst), "l"(src));
}
__device__ __forceinline__ void cp_commit() {
    asm volatile("cp.async.commit_group;\n");
}
template <int N> __device__ __forceinline__ void cp_wait() {
    asm volatile("cp.async.wait_group %0;\n" :: "n"(N));
}
__device__ __forceinline__ void ldsm_x4(uint32_t r[4], uint32_t addr) {
    asm volatile("ldmatrix.sync.aligned.m8n8.x4.shared.b16 {%0,%1,%2,%3}, [%4];\n"
                 : "=r"(r[0]), "=r"(r[1]), "=r"(r[2]), "=r"(r[3]) : "r"(addr));
}
__device__ __forceinline__ void ldsm_x4_t(uint32_t r[4], uint32_t addr) {
    asm volatile("ldmatrix.sync.aligned.m8n8.x4.trans.shared.b16 {%0,%1,%2,%3}, [%4];\n"
                 : "=r"(r[0]), "=r"(r[1]), "=r"(r[2]), "=r"(r[3]) : "r"(addr));
}
__device__ __forceinline__ void mma_bf16(float c[4], const uint32_t a[4],
                                         uint32_t b0, uint32_t b1) {
    asm volatile(
        "mma.sync.aligned.m16n8k16.row.col.f32.bf16.bf16.f32 "
        "{%0,%1,%2,%3},{%4,%5,%6,%7},{%8,%9},{%0,%1,%2,%3};\n"
        : "+f"(c[0]), "+f"(c[1]), "+f"(c[2]), "+f"(c[3])
        : "r"(a[0]), "r"(a[1]), "r"(a[2]), "r"(a[3]), "r"(b0), "r"(b1));
}
__device__ __forceinline__ uint32_t packbf(float lo, float hi) {
    uint32_t r;
    asm("cvt.rn.bf16x2.f32 %0, %1, %2;\n" : "=r"(r) : "f"(hi), "f"(lo));
    return r;
}
__device__ __forceinline__ uint32_t s2u(const void* p) {
    return (uint32_t)__cvta_generic_to_shared(p);
}

// ---------------------------------------------------------------------------
// W0: transpose weights to [N][K] bf16.
// ---------------------------------------------------------------------------
__global__ void wconv(const float* __restrict__ wq, const float* __restrict__ wp) {
    const int idx = blockIdx.x * 256 + threadIdx.x;   // 768*256 threads
    const int n = idx >> 8, k = idx & 255;
    g_WTq[idx] = __float2bfloat16(wq[k * 768 + n]);
    if (n < 256) g_WTp[idx] = __float2bfloat16(wp[k * 256 + n]);
}

// ---------------------------------------------------------------------------
// K1: LayerNorm over C + cyclic shift (-4,-4) + window partition -> bf16 Y.
// ---------------------------------------------------------------------------
__global__ void k1_ln_roll_part(const float* __restrict__ x,
                                const float* __restrict__ gamma,
                                const float* __restrict__ beta,
                                __nv_bfloat16* __restrict__ Y) {
    __shared__ float tile[32][257];
    const int b  = blockIdx.z;
    const int h  = blockIdx.y;
    const int w0 = blockIdx.x * 32;
    const int t  = threadIdx.x;
    const int wl = t & 31;
    const int co = t >> 5;

    const float* xb = x + (long)b * Cdim * Hdim * Wdim;
    #pragma unroll
    for (int cb = 0; cb < Cdim; cb += 8) {
        const int c = cb + co;
        tile[wl][c] = xb[((long)c * Hdim + h) * Wdim + w0 + wl];
    }
    __syncthreads();

    const int p = t >> 3, sub = t & 7;
    float s = 0.f, ss = 0.f;
    #pragma unroll
    for (int c = sub; c < Cdim; c += 8) {
        const float v = tile[p][c];
        s += v; ss += v * v;
    }
    #pragma unroll
    for (int off = 4; off > 0; off >>= 1) {
        s  += __shfl_xor_sync(0xffffffffu, s,  off);
        ss += __shfl_xor_sync(0xffffffffu, ss, off);
    }
    const float mean = s * (1.f / Cdim);
    const float var  = ss * (1.f / Cdim) - mean * mean;
    const float inv  = rsqrtf(var + 1e-5f);
    #pragma unroll
    for (int c = sub; c < Cdim; c += 8)
        tile[p][c] = (tile[p][c] - mean) * inv * gamma[c] + beta[c];
    __syncthreads();

    const int h2 = (h - 4) & 127;
    #pragma unroll 4
    for (int p2 = 0; p2 < 32; p2++) {
        const int w2 = (w0 + p2 - 4) & 127;
        const long row = (((long)b * 16 + (h2 >> 3)) * 16 + (w2 >> 3)) * 64
                         + (h2 & 7) * 8 + (w2 & 7);
        Y[row * Cdim + t] = __float2bfloat16(tile[p2][t]);
    }
}

// ---------------------------------------------------------------------------
// K2: bf16 tensor-core GEMM: C[M,N] = A[M,256] @ WT[N][256]^T + bias -> bf16.
// Block 128x128, BK=32, 8 warps, warp tile 64x32, cp.async double buffer.
// ---------------------------------------------------------------------------
#define GP 40   // smem row pitch in halves (80 B: 16B-aligned, conflict-free)

__global__ __launch_bounds__(256)
void bf16_gemm_qkv(const __nv_bfloat16* __restrict__ A,
                   const __nv_bfloat16* __restrict__ WT,
                   const float* __restrict__ bias,
                   __nv_bfloat16* __restrict__ Cb, int N) {
    __shared__ __nv_bfloat16 As[2][128 * GP];
    __shared__ __nv_bfloat16 Bs[2][128 * GP];
    const int K = 256;

    const int t    = threadIdx.x;
    const int warp = t >> 5;
    const int lane = t & 31;
    const int gid  = lane >> 2;
    const int tig  = lane & 3;
    const int wm   = (warp >> 2) * 64;
    const int wn   = (warp & 3) * 32;
    const int bm   = blockIdx.y * 128;
    const int bn   = blockIdx.x * 128;

    const uint32_t asb = s2u(&As[0][0]);
    const uint32_t bsb = s2u(&Bs[0][0]);

    auto loadStage = [&](int st, int k0) {
        #pragma unroll
        for (int i = 0; i < 2; i++) {
            const int ci  = t + i * 256;
            const int row = ci >> 2;
            const int kc  = (ci & 3) * 8;
            cp16(asb + (st * 128 * GP + row * GP + kc) * 2,
                 A + (long)(bm + row) * K + k0 + kc);
            cp16(bsb + (st * 128 * GP + row * GP + kc) * 2,
                 WT + (long)(bn + row) * K + k0 + kc);
        }
        cp_commit();
    };

    float acc[4][4][4];
    #pragma unroll
    for (int i = 0; i < 4; i++)
        #pragma unroll
        for (int j = 0; j < 4; j++)
            #pragma unroll
            for (int r = 0; r < 4; r++) acc[i][j][r] = 0.f;

    loadStage(0, 0);

    const int r16  = lane & 15;
    const int hsel = (lane >> 4) << 3;
    const int sel  = lane >> 3, l8 = lane & 7;

    #pragma unroll 1
    for (int kt = 0; kt < 8; kt++) {
        cp_wait<0>();
        __syncthreads();
        if (kt + 1 < 8) loadStage((kt + 1) & 1, (kt + 1) * 32);

        const int st = kt & 1;
        #pragma unroll
        for (int ks = 0; ks < 2; ks++) {
            uint32_t af[4][4];
            #pragma unroll
            for (int mt = 0; mt < 4; mt++)
                ldsm_x4(af[mt], asb + (st * 128 * GP
                        + (wm + mt * 16 + r16) * GP + ks * 16 + hsel) * 2);
            #pragma unroll
            for (int np = 0; np < 2; np++) {
                const int brow = wn + np * 16 + ((sel & 2) ? 8 : 0) + l8;
                const int bcol = ks * 16 + ((sel & 1) ? 8 : 0);
                uint32_t bf[4];
                ldsm_x4(bf, bsb + (st * 128 * GP + brow * GP + bcol) * 2);
                #pragma unroll
                for (int mt = 0; mt < 4; mt++) {
                    mma_bf16(acc[mt][np * 2],     af[mt], bf[0], bf[1]);
                    mma_bf16(acc[mt][np * 2 + 1], af[mt], bf[2], bf[3]);
                }
            }
        }
        __syncthreads();
    }

    #pragma unroll
    for (int nt = 0; nt < 4; nt++) {
        const int col = bn + wn + nt * 8 + 2 * tig;
        const float b0 = bias[col], b1 = bias[col + 1];
        #pragma unroll
        for (int mt = 0; mt < 4; mt++) {
            const long row = bm + wm + mt * 16 + gid;
            *(uint32_t*)&Cb[row * N + col] =
                packbf(acc[mt][nt][0] + b0, acc[mt][nt][1] + b1);
            *(uint32_t*)&Cb[(row + 8) * N + col] =
                packbf(acc[mt][nt][2] + b0, acc[mt][nt][3] + b1);
        }
    }
}

// ---------------------------------------------------------------------------
// K4E: proj GEMM fused with epilogue: out[b,c,h,w] = 2*(P + x) directly in
// BCHW with window-reverse + roll(+4,+4). P = O @ w_proj^T + bias.
// ---------------------------------------------------------------------------
__global__ __launch_bounds__(256)
void bf16_gemm_proj_epi(const __nv_bfloat16* __restrict__ A,
                        const __nv_bfloat16* __restrict__ WT,
                        const float* __restrict__ bias,
                        const float* __restrict__ x,
                        float* __restrict__ out) {
    __shared__ __nv_bfloat16 As[2][128 * GP];
    __shared__ __nv_bfloat16 Bs[2][128 * GP];
    const int K = 256;

    const int t    = threadIdx.x;
    const int warp = t >> 5;
    const int lane = t & 31;
    const int gid  = lane >> 2;
    const int tig  = lane & 3;
    const int wm   = (warp >> 2) * 64;
    const int wn   = (warp & 3) * 32;
    const int bm   = blockIdx.y * 128;
    const int bn   = blockIdx.x * 128;

    const uint32_t asb = s2u(&As[0][0]);
    const uint32_t bsb = s2u(&Bs[0][0]);

    auto loadStage = [&](int st, int k0) {
        #pragma unroll
        for (int i = 0; i < 2; i++) {
            const int ci  = t + i * 256;
            const int row = ci >> 2;
            const int kc  = (ci & 3) * 8;
            cp16(asb + (st * 128 * GP + row * GP + kc) * 2,
                 A + (long)(bm + row) * K + k0 + kc);
            cp16(bsb + (st * 128 * GP + row * GP + kc) * 2,
                 WT + (long)(bn + row) * K + k0 + kc);
        }
        cp_commit();
    };

    float acc[4][4][4];
    #pragma unroll
    for (int i = 0; i < 4; i++)
        #pragma unroll
        for (int j = 0; j < 4; j++)
            #pragma unroll
            for (int r = 0; r < 4; r++) acc[i][j][r] = 0.f;

    loadStage(0, 0);

    const int r16  = lane & 15;
    const int hsel = (lane >> 4) << 3;
    const int sel  = lane >> 3, l8 = lane & 7;

    #pragma unroll 1
    for (int kt = 0; kt < 8; kt++) {
        cp_wait<0>();
        __syncthreads();
        if (kt + 1 < 8) loadStage((kt + 1) & 1, (kt + 1) * 32);

        const int st = kt & 1;
        #pragma unroll
        for (int ks = 0; ks < 2; ks++) {
            uint32_t af[4][4];
            #pragma unroll
            for (int mt = 0; mt < 4; mt++)
                ldsm_x4(af[mt], asb + (st * 128 * GP
                        + (wm + mt * 16 + r16) * GP + ks * 16 + hsel) * 2);
            #pragma unroll
            for (int np = 0; np < 2; np++) {
                const int brow = wn + np * 16 + ((sel & 2) ? 8 : 0) + l8;
                const int bcol = ks * 16 + ((sel & 1) ? 8 : 0);
                uint32_t bf[4];
                ldsm_x4(bf, bsb + (st * 128 * GP + brow * GP + bcol) * 2);
                #pragma unroll
                for (int mt = 0; mt < 4; mt++) {
                    mma_bf16(acc[mt][np * 2],     af[mt], bf[0], bf[1]);
                    mma_bf16(acc[mt][np * 2 + 1], af[mt], bf[2], bf[3]);
                }
            }
        }
        __syncthreads();
    }

    // fused epilogue: window-reverse + roll + residual, scattered to BCHW
    #pragma unroll
    for (int mt = 0; mt < 4; mt++) {
        #pragma unroll
        for (int rh = 0; rh < 2; rh++) {
            const int row = bm + wm + mt * 16 + gid + rh * 8;
            const int win = row >> 6;
            const int n   = row & 63;
            const int b   = win >> 8;
            const int wh  = (win >> 4) & 15;
            const int ww  = win & 15;
            const int h   = (wh * 8 + (n >> 3) + 4) & 127;
            const int w   = (ww * 8 + (n & 7) + 4) & 127;
            const long pbase = ((long)b * Cdim) * (Hdim * Wdim) + h * Wdim + w;
            #pragma unroll
            for (int nt = 0; nt < 4; nt++) {
                const int c0 = bn + wn + nt * 8 + 2 * tig;
                const long i0 = pbase + (long)c0 * (Hdim * Wdim);
                const long i1 = i0 + (Hdim * Wdim);
                out[i0] = 2.f * (acc[mt][nt][rh * 2]     + bias[c0]     + x[i0]);
                out[i1] = 2.f * (acc[mt][nt][rh * 2 + 1] + bias[c0 + 1] + x[i1]);
            }
        }
    }
}

// ---------------------------------------------------------------------------
// K3: persistent tensor-core windowed attention.
// grid = 148 CTAs x 512 threads; each CTA processes windows cta, cta+148, ...
// Double-buffered swizzled smem (2 x 96 KB): prefetch window i+1 via cp.async
// while computing window i -> DRAM stays busy.
// Layout: per (qkv,head) tile = 64 rows x 64 B; 16B chunk c at row r lives at
// r*64 + ((c ^ ((r>>1)&3))<<4)  -> all 8 LDSM rows hit distinct 16B groups.
// ---------------------------------------------------------------------------
#define WTILE_B 4096            // bytes per (qkv, head) tile
#define BUF_B   (24 * WTILE_B)  // 98304 bytes per window buffer

__device__ __forceinline__ uint32_t swz(int row, int chunk) {
    return (uint32_t)(row * 64 + ((chunk ^ ((row >> 1) & 3)) << 4));
}

__global__ __launch_bounds__(512, 1)
void k3_attention(const __nv_bfloat16* __restrict__ QKV,
                  __nv_bfloat16* __restrict__ O) {
    extern __shared__ __nv_bfloat16 smem[];
    const int t     = threadIdx.x;
    const int wid   = t >> 5;
    const int head  = wid >> 1;
    const int mhalf = wid & 1;      // rows [mhalf*32, mhalf*32+32)
    const int lane  = t & 31;
    const int gid   = lane >> 2;
    const int tig   = lane & 3;

    const uint32_t sb = s2u(smem);

    const int r16  = lane & 15;
    const int hs2  = lane >> 4;        // 0/1: k-half chunk select
    const int sel  = lane >> 3, l8 = lane & 7;
    const int mb   = mhalf * 32;
    const float scale = 0.17677669529663689f;

    auto loadWin = [&](int win, int buf) {
        const __nv_bfloat16* src = QKV + (long)win * (64 * 768);
        const uint32_t db = sb + buf * BUF_B;
        #pragma unroll
        for (int i = 0; i < 12; i++) {
            const int ci    = i * 512 + t;      // 0..6143 16B chunks
            const int token = ci / 96;
            const int c2    = ci % 96;
            const int qkv   = c2 >> 5;
            const int rest  = c2 & 31;
            const int hh    = rest >> 2;
            const int ch    = rest & 3;
            cp16(db + (qkv * 8 + hh) * WTILE_B + swz(token, ch),
                 src + (long)token * 768 + qkv * 256 + hh * 32 + ch * 8);
        }
    };

    const int w0 = blockIdx.x;
    if (w0 < NWIN) loadWin(w0, 0);
    cp_commit();

    int i = 0;
    for (int win = w0; win < NWIN; win += NSM, i++) {
        const int wnext = win + NSM;
        if (wnext < NWIN) loadWin(wnext, (i + 1) & 1);
        cp_commit();
        cp_wait<1>();
        __syncthreads();

        const int buf = i & 1;
        const uint32_t qb = sb + buf * BUF_B + head * WTILE_B;
        const uint32_t kb = sb + buf * BUF_B + (8 + head) * WTILE_B;
        const uint32_t vb = sb + buf * BUF_B + (16 + head) * WTILE_B;

        // ---- S = Q K^T (32x64 rows for this warp), fp32 accum
        float sc[2][8][4];
        #pragma unroll
        for (int mt = 0; mt < 2; mt++)
            #pragma unroll
            for (int nt = 0; nt < 8; nt++)
                #pragma unroll
                for (int r = 0; r < 4; r++) sc[mt][nt][r] = 0.f;

        #pragma unroll
        for (int ks = 0; ks < 2; ks++) {
            uint32_t af[2][4];
            #pragma unroll
            for (int mt = 0; mt < 2; mt++)
                ldsm_x4(af[mt], qb + swz(mb + mt * 16 + r16, ks * 2 + hs2));
            #pragma unroll
            for (int np = 0; np < 4; np++) {
                const int brow = np * 16 + ((sel & 2) ? 8 : 0) + l8;
                uint32_t bf[4];
                ldsm_x4(bf, kb + swz(brow, ks * 2 + (sel & 1)));
                #pragma unroll
                for (int mt = 0; mt < 2; mt++) {
                    mma_bf16(sc[mt][np * 2],     af[mt], bf[0], bf[1]);
                    mma_bf16(sc[mt][np * 2 + 1], af[mt], bf[2], bf[3]);
                }
            }
        }

        // ---- softmax over rows (quad shuffles)
        float ilo[2], ihi[2];
        #pragma unroll
        for (int mt = 0; mt < 2; mt++) {
            float mlo = -1e30f, mhi = -1e30f;
            #pragma unroll
            for (int nt = 0; nt < 8; nt++) {
                mlo = fmaxf(mlo, fmaxf(sc[mt][nt][0], sc[mt][nt][1]));
                mhi = fmaxf(mhi, fmaxf(sc[mt][nt][2], sc[mt][nt][3]));
            }
            mlo = fmaxf(mlo, __shfl_xor_sync(0xffffffffu, mlo, 1));
            mlo = fmaxf(mlo, __shfl_xor_sync(0xffffffffu, mlo, 2));
            mhi = fmaxf(mhi, __shfl_xor_sync(0xffffffffu, mhi, 1));
            mhi = fmaxf(mhi, __shfl_xor_sync(0xffffffffu, mhi, 2));
            float slo = 0.f, shi = 0.f;
            #pragma unroll
            for (int nt = 0; nt < 8; nt++) {
                sc[mt][nt][0] = __expf(scale * (sc[mt][nt][0] - mlo));
                sc[mt][nt][1] = __expf(scale * (sc[mt][nt][1] - mlo));
                sc[mt][nt][2] = __expf(scale * (sc[mt][nt][2] - mhi));
                sc[mt][nt][3] = __expf(scale * (sc[mt][nt][3] - mhi));
                slo += sc[mt][nt][0] + sc[mt][nt][1];
                shi += sc[mt][nt][2] + sc[mt][nt][3];
            }
            slo += __shfl_xor_sync(0xffffffffu, slo, 1);
            slo += __shfl_xor_sync(0xffffffffu, slo, 2);
            shi += __shfl_xor_sync(0xffffffffu, shi, 1);
            shi += __shfl_xor_sync(0xffffffffu, shi, 2);
            ilo[mt] = 1.f / slo;
            ihi[mt] = 1.f / shi;
        }

        // ---- O = P V (32x32 for this warp)
        float oc[2][4][4];
        #pragma unroll
        for (int mt = 0; mt < 2; mt++)
            #pragma unroll
            for (int nt = 0; nt < 4; nt++)
                #pragma unroll
                for (int r = 0; r < 4; r++) oc[mt][nt][r] = 0.f;

        #pragma unroll
        for (int ks = 0; ks < 4; ks++) {   // token chunks of 16
            uint32_t pa[2][4];
            #pragma unroll
            for (int mt = 0; mt < 2; mt++) {
                pa[mt][0] = packbf(sc[mt][2 * ks][0] * ilo[mt], sc[mt][2 * ks][1] * ilo[mt]);
                pa[mt][1] = packbf(sc[mt][2 * ks][2] * ihi[mt], sc[mt][2 * ks][3] * ihi[mt]);
                pa[mt][2] = packbf(sc[mt][2 * ks + 1][0] * ilo[mt], sc[mt][2 * ks + 1][1] * ilo[mt]);
                pa[mt][3] = packbf(sc[mt][2 * ks + 1][2] * ihi[mt], sc[mt][2 * ks + 1][3] * ihi[mt]);
            }
            #pragma unroll
            for (int dp = 0; dp < 2; dp++) {  // dim chunks of 16
                const int vrow = ks * 16 + ((sel & 1) ? 8 : 0) + l8;
                uint32_t vf[4];
                ldsm_x4_t(vf, vb + swz(vrow, dp * 2 + ((sel & 2) >> 1)));
                #pragma unroll
                for (int mt = 0; mt < 2; mt++) {
                    mma_bf16(oc[mt][dp * 2],     pa[mt], vf[0], vf[1]);
                    mma_bf16(oc[mt][dp * 2 + 1], pa[mt], vf[2], vf[3]);
                }
            }
        }

        // ---- store O bf16 [row][256]
        #pragma unroll
        for (int mt = 0; mt < 2; mt++) {
            const long row = (long)win * 64 + mb + mt * 16 + gid;
            #pragma unroll
            for (int nt = 0; nt < 4; nt++) {
                const int col = head * 32 + nt * 8 + 2 * tig;
                *(uint32_t*)&O[row * 256 + col] =
                    packbf(oc[mt][nt][0], oc[mt][nt][1]);
                *(uint32_t*)&O[(row + 8) * 256 + col] =
                    packbf(oc[mt][nt][2], oc[mt][nt][3]);
            }
        }
        __syncthreads();   // all warps done with buf before it is reloaded
    }
}

// ---------------------------------------------------------------------------
extern "C" void kernel_launch(void* const* d_in, const int* in_sizes, int n_in,
                              void* d_out, int out_size) {
    const float* x      = (const float*)d_in[0];
    const float* n1g    = (const float*)d_in[1];
    const float* n1b    = (const float*)d_in[2];
    const float* w_qkv  = (const float*)d_in[3];
    const float* b_qkv  = (const float*)d_in[4];
    const float* w_proj = (const float*)d_in[5];
    const float* b_proj = (const float*)d_in[6];
    float* out = (float*)d_out;

    __nv_bfloat16 *Y, *QKV, *Obuf, *WTq, *WTp;
    cudaGetSymbolAddress((void**)&Y,    g_Y);
    cudaGetSymbolAddress((void**)&QKV,  g_QKV);
    cudaGetSymbolAddress((void**)&Obuf, g_O);
    cudaGetSymbolAddress((void**)&WTq,  g_WTq);
    cudaGetSymbolAddress((void**)&WTp,  g_WTp);

    const int att_smem = 2 * BUF_B;  // 196608 B
    cudaFuncSetAttribute(k3_attention,
                         cudaFuncAttributeMaxDynamicSharedMemorySize, att_smem);

    // W0: weight transpose+convert
    wconv<<<768, 256>>>(w_qkv, w_proj);

    // K1: LN + shift + window partition -> bf16
    k1_ln_roll_part<<<dim3(4, 128, 8), 256>>>(x, n1g, n1b, Y);

    // K2: QKV GEMM (bf16 tensor cores)
    bf16_gemm_qkv<<<dim3(6, 1024), 256>>>(Y, WTq, b_qkv, QKV, 768);

    // K3: persistent double-buffered windowed attention
    k3_attention<<<NSM, 512, att_smem>>>(QKV, Obuf);

    // K4E: proj GEMM + fused reverse/roll/residual epilogue -> BCHW out
    bf16_gemm_proj_epi<<<dim3(2, 1024), 256>>>(Obuf, WTp, b_proj, x, out);
}